// round 15
// baseline (speedup 1.0000x reference)
#include <cuda_runtime.h>
#include <cuda_bf16.h>
#include <math.h>
#include <stdint.h>

#define B_    64
#define S_    512
#define H_    256
#define IN_   512
#define G4    1024      // 4*H
#define NC    1000
#define AD    80
#define MTOT  (B_*S_)   // 32768
#define RES_ELEMS (MTOT*NC)

// ---------------- scratch (device globals) ---------------------------------
__device__ float g_P1[1000 * G4];
__device__ float g_P0[1000 * G4];
__device__ float g_qb[2 * G4];
__device__ float g_out  [MTOT * H_];
__device__ float g_att  [MTOT];
__device__ __nv_bfloat16 g_finH[MTOT * IN_];
__device__ __nv_bfloat16 g_finL[MTOT * IN_];
__device__ __nv_bfloat16 g_fwH[1024 * IN_];
__device__ __nv_bfloat16 g_fwL[1024 * IN_];
__device__ float g_fcb[1024];

// ---------------- helpers ---------------------------------------------------
__device__ __forceinline__ unsigned long long fma2(unsigned long long a,
                                                   unsigned long long b,
                                                   unsigned long long c) {
    unsigned long long d;
    asm("fma.rn.f32x2 %0, %1, %2, %3;" : "=l"(d) : "l"(a), "l"(b), "l"(c));
    return d;
}
__device__ __forceinline__ float f2sum(unsigned long long v) {
    float lo, hi;
    asm("mov.b64 {%0, %1}, %2;" : "=f"(lo), "=f"(hi) : "l"(v));
    return lo + hi;
}
__device__ __forceinline__ uint32_t s2u(const void* p) {
    uint32_t a;
    asm("{ .reg .u64 t; cvta.to.shared.u64 t, %1; cvt.u32.u64 %0, t; }"
        : "=r"(a) : "l"(p));
    return a;
}
__device__ __forceinline__ float tanh_a(float x) {
    float y;
    asm("tanh.approx.f32 %0, %1;" : "=f"(y) : "f"(x));
    return y;
}
__device__ __forceinline__ float sig_a(float x) {
    return fmaf(tanh_a(0.5f * x), 0.5f, 0.5f);
}

#define SWZ(o) ((o) ^ (((o) >> 3) & 0x70))

__device__ __forceinline__ void cpa16(uint32_t dst, const void* src) {
    asm volatile("cp.async.cg.shared.global [%0], [%1], 16;" :: "r"(dst), "l"(src) : "memory");
}
#define CPA_COMMIT() asm volatile("cp.async.commit_group;" ::: "memory")
template<int N> __device__ __forceinline__ void cpa_wait() {
    asm volatile("cp.async.wait_group %0;" :: "n"(N) : "memory");
}

__device__ __forceinline__ void ldsm4(uint32_t (&r)[4], uint32_t addr) {
    asm volatile("ldmatrix.sync.aligned.m8n8.x4.shared.b16 {%0,%1,%2,%3}, [%4];"
        : "=r"(r[0]), "=r"(r[1]), "=r"(r[2]), "=r"(r[3]) : "r"(addr));
}
__device__ __forceinline__ void mma16816(float (&d)[4], const uint32_t (&a)[4],
                                         uint32_t b0, uint32_t b1) {
    asm volatile("mma.sync.aligned.m16n8k16.row.col.f32.bf16.bf16.f32 "
        "{%0,%1,%2,%3}, {%4,%5,%6,%7}, {%8,%9}, {%0,%1,%2,%3};"
        : "+f"(d[0]), "+f"(d[1]), "+f"(d[2]), "+f"(d[3])
        : "r"(a[0]), "r"(a[1]), "r"(a[2]), "r"(a[3]), "r"(b0), "r"(b1));
}

#define MBAR_INIT(a, cnt) asm volatile("mbarrier.init.shared.b64 [%0], %1;" :: "r"(a), "r"(cnt) : "memory")
#define MBAR_EXPECT(a, bytes) asm volatile("mbarrier.arrive.expect_tx.shared.b64 _, [%0], %1;" :: "r"(a), "r"(bytes) : "memory")
__device__ __forceinline__ void mbar_wait_cluster(uint32_t mbar, uint32_t parity) {
    uint32_t done;
    asm volatile(
        "{\n\t.reg .pred p;\n\t"
        "mbarrier.try_wait.parity.acquire.cluster.shared::cta.b64 p, [%1], %2;\n\t"
        "selp.b32 %0, 1, 0, p;\n\t}"
        : "=r"(done) : "r"(mbar), "r"(parity) : "memory");
    if (!done) {
        asm volatile(
            "{\n\t.reg .pred P1;\n\t"
            "WL_%=:\n\t"
            "mbarrier.try_wait.parity.acquire.cluster.shared::cta.b64 P1, [%0], %1, 0x989680;\n\t"
            "@P1 bra.uni WD_%=;\n\t"
            "bra.uni WL_%=;\n\t"
            "WD_%=:\n\t}"
            :: "r"(mbar), "r"(parity) : "memory");
    }
}
__device__ __forceinline__ void st_async_u32(uint32_t addr, uint32_t val, uint32_t mbar) {
    asm volatile("st.async.shared::cluster.mbarrier::complete_tx::bytes.b32 [%0], %1, [%2];"
                 :: "r"(addr), "r"(val), "r"(mbar) : "memory");
}

__device__ __forceinline__ void packhl(float2 v, uint32_t& hi, uint32_t& lo) {
    __nv_bfloat16 h0 = __float2bfloat16(v.x), h1 = __float2bfloat16(v.y);
    hi = ((uint32_t)__bfloat16_as_ushort(h1) << 16) | __bfloat16_as_ushort(h0);
    __nv_bfloat16 l0 = __float2bfloat16(v.x - __bfloat162float(h0));
    __nv_bfloat16 l1 = __float2bfloat16(v.y - __bfloat162float(h1));
    lo = ((uint32_t)__bfloat16_as_ushort(l1) << 16) | __bfloat16_as_ushort(l0);
}

// ---------------------------------------------------------------------------
__global__ void qbias_kernel(const float* __restrict__ Wih,
                             const float* __restrict__ answer_emb,
                             const float* __restrict__ bih,
                             const float* __restrict__ bhh) {
    int idx = blockIdx.x * blockDim.x + threadIdx.x;
    if (idx >= 2 * G4) return;
    int a = idx >> 10;
    int row = idx & (G4 - 1);
    int off = (a == 1) ? H_ : 0;
    float s = bih[row] + bhh[row];
    const float* wr = Wih + (size_t)row * IN_ + off;
    const float* ar = answer_emb + a * H_;
#pragma unroll 4
    for (int k = 0; k < H_; k++) s += wr[k] * ar[k];
    g_qb[idx] = s;
}

// ---------------------------------------------------------------------------
__global__ void embed_kernel(const int* __restrict__ skill,
                             const int* __restrict__ answer,
                             const float* __restrict__ skill_emb,
                             const float* __restrict__ answer_emb,
                             float* __restrict__ sa) {
    int r = blockIdx.x;
    int t = threadIdx.x;
    int sk = skill[r];
    int an = answer[r];
    float se = skill_emb[sk * H_ + t];
    float ae = answer_emb[an * H_ + t];
    float* o = sa + (size_t)r * IN_;
    if (an == 1) { o[t] = se; o[H_ + t] = ae; }
    else         { o[t] = ae; o[H_ + t] = se; }
    if (t == 0) g_att[r] = 0.f;
}

// ---------------------------------------------------------------------------
__global__ void convw_kernel(const float* __restrict__ fc_W,
                             const float* __restrict__ fc_b) {
    int idx = blockIdx.x * blockDim.x + threadIdx.x;
    if (idx >= 1024 * IN_) return;
    int row = idx >> 9;
    float x = (row < NC) ? fc_W[(size_t)row * IN_ + (idx & 511)] : 0.f;
    __nv_bfloat16 h = __float2bfloat16(x);
    g_fwH[idx] = h;
    g_fwL[idx] = __float2bfloat16(x - __bfloat162float(h));
    if (idx < 1024) g_fcb[idx] = (idx < NC) ? fc_b[idx] : 0.f;
}

// ---------------------------------------------------------------------------
// fp32 GEMM (f32x2) — P tables (act 0) and mlp+attdot fusion (act 3).
__global__ void gemm_kernel(const float* __restrict__ A, int lda,
                            const float* __restrict__ Bm, int ldb,
                            const float* __restrict__ bias,
                            float* __restrict__ C,
                            int M, int N, int K, int act,
                            const float* __restrict__ simW,
                            float* __restrict__ attO) {
    __shared__ float2 As2[8][64];
    __shared__ float2 Bs2[8][64];
    __shared__ float simW_s[128];

    int tid = threadIdx.x;
    int tx = tid & 15;
    int ty = tid >> 4;
    int rowBase = blockIdx.y * 64;
    int colBase = blockIdx.x * 64;
    int ldRow = tid >> 2;
    int ldCol = (tid & 3) * 4;

    if (act == 3 && tid < 128) {
        int c = colBase + tid;
        simW_s[tid] = (tid < 64 && c < N) ? simW[c] : 0.f;
    }

    unsigned long long acc[4][4];
#pragma unroll
    for (int i = 0; i < 4; i++)
#pragma unroll
        for (int j = 0; j < 4; j++) acc[i][j] = 0ULL;

    for (int k0 = 0; k0 < K; k0 += 16) {
        int arow = rowBase + ldRow; if (arow > M - 1) arow = M - 1;
        float4 av = *reinterpret_cast<const float4*>(A + (size_t)arow * lda + k0 + ldCol);
        As2[ldCol / 2][ldRow]     = make_float2(av.x, av.y);
        As2[ldCol / 2 + 1][ldRow] = make_float2(av.z, av.w);
        int n = colBase + ldRow;
        float4 bv = make_float4(0.f, 0.f, 0.f, 0.f);
        if (n < N)
            bv = *reinterpret_cast<const float4*>(Bm + (size_t)n * ldb + k0 + ldCol);
        Bs2[ldCol / 2][ldRow]     = make_float2(bv.x, bv.y);
        Bs2[ldCol / 2 + 1][ldRow] = make_float2(bv.z, bv.w);
        __syncthreads();

#pragma unroll
        for (int kk2 = 0; kk2 < 8; kk2++) {
            ulonglong2 aA = *reinterpret_cast<const ulonglong2*>(&As2[kk2][ty * 4]);
            ulonglong2 aB = *reinterpret_cast<const ulonglong2*>(&As2[kk2][ty * 4 + 2]);
            unsigned long long a2[4] = {aA.x, aA.y, aB.x, aB.y};
            unsigned long long b2[4];
#pragma unroll
            for (int j = 0; j < 4; j++)
                b2[j] = *reinterpret_cast<const unsigned long long*>(&Bs2[kk2][tx + 16 * j]);
#pragma unroll
            for (int i = 0; i < 4; i++)
#pragma unroll
                for (int j = 0; j < 4; j++)
                    acc[i][j] = fma2(a2[i], b2[j], acc[i][j]);
        }
        __syncthreads();
    }

    if (act == 3) {
#pragma unroll
        for (int i = 0; i < 4; i++) {
            int row = rowBase + ty * 4 + i;
            float part = 0.f;
#pragma unroll
            for (int j = 0; j < 4; j++) {
                int lc = tx + 16 * j;
                int col = colBase + lc;
                if (col < N) {
                    float v = f2sum(acc[i][j]) + bias[col];
                    part = fmaf(tanh_a(v), simW_s[lc], part);
                }
            }
            atomicAdd(attO + row, part);
        }
        return;
    }

#pragma unroll
    for (int i = 0; i < 4; i++) {
        int row = rowBase + ty * 4 + i;
        if (row >= M) continue;
#pragma unroll
        for (int j = 0; j < 4; j++) {
            int col = colBase + tx + 16 * j;
            if (col < N) {
                float v = f2sum(acc[i][j]);
                if (bias) v += bias[col];
                C[(size_t)row * N + col] = v;
            }
        }
    }
}

// ---------------------------------------------------------------------------
// LSTM v11: FOUR-group pipeline. 4 clusters x 8 CTAs x 16 batches (4 groups
// of 4). Sections [g][buf]: per step, 4x [wait mma update send] — each group's
// exchange latency hides under 3 other sections. Update half A (tid<128) owns
// groups 0,2; half B owns 1,3; c-state lives in registers (2 per thread).
#define HP_STRIDE 132                 // u64 per batch
#define HP_GB     (4 * HP_STRIDE)     // 528 u64 per (group,buffer) section
// floats: mbar 16 | hp 8*528 u64 = 8448 | gp 640 | sk 8192 | an 8192
#define LSTM_SMEM ((16 + 8448 + 640 + 8192 + 8192) * 4)

__global__ void __cluster_dims__(8, 1, 1) __launch_bounds__(256, 1)
lstm_kernel(const int* __restrict__ skill, const int* __restrict__ answer,
            const float* __restrict__ Whh, float* __restrict__ out) {
    extern __shared__ float smem[];
    uint32_t smem_u32 = s2u(smem);
    // mbar(sec) = smem_u32 + sec*8, sec = g*2+buf (8 mbarriers, 64B)
    unsigned long long* hp = (unsigned long long*)(smem + 16);  // [8 sec][528]
    float* gp  = smem + 16 + 8448;       // [128 rows][5]
    int* sk_s  = (int*)(gp + 640);       // [16][512]
    int* an_s  = sk_s + 16 * S_;         // [16][512]

    int tid  = threadIdx.x;
    int w    = tid >> 5;
    int l    = tid & 31;
    int rank = blockIdx.x & 7;
    int cid  = blockIdx.x >> 3;

    // ---- one-time: Whh -> bf16 hi/lo A-fragments in registers ----
    uint32_t ah[16][4], al[16][4];
    {
        int rl0 = 16 * w + (l >> 2);
        int rl1 = rl0 + 8;
        size_t rowA = (size_t)((rl0 >> 5) * H_ + rank * 32 + (rl0 & 31)) * H_;
        size_t rowB = (size_t)((rl1 >> 5) * H_ + rank * 32 + (rl1 & 31)) * H_;
#pragma unroll
        for (int t = 0; t < 16; t++) {
            int k = t * 16 + (l & 3) * 2;
            packhl(*(const float2*)(Whh + rowA + k),     ah[t][0], al[t][0]);
            packhl(*(const float2*)(Whh + rowB + k),     ah[t][1], al[t][1]);
            packhl(*(const float2*)(Whh + rowA + k + 8), ah[t][2], al[t][2]);
            packhl(*(const float2*)(Whh + rowB + k + 8), ah[t][3], al[t][3]);
        }
    }

    // init smem
    for (int i = tid; i < 8 * HP_GB; i += 256) hp[i] = 0ULL;
    for (int i = tid; i < 16 * S_; i += 256) {
        int bb = i >> 9, ss = i & (S_ - 1);
        int ridx = (cid * 16 + bb) * S_ + ss;
        sk_s[i] = skill[ridx];
        an_s[i] = answer[ridx];
    }
    if (tid == 0) {
#pragma unroll
        for (int m = 0; m < 8; m++) MBAR_INIT(smem_u32 + m * 8, 1);
    }
    __syncthreads();
    asm volatile("barrier.cluster.arrive.aligned;" ::: "memory");
    asm volatile("barrier.cluster.wait.aligned;" ::: "memory");

    const int half = tid >> 7;           // 0: groups {0,2}; 1: groups {1,3}
    const int utid = tid & 127;
    const int uu   = utid & 31;
    const int ubb  = utid >> 5;          // batch within group
    const int n4   = (l >> 2) & 3;       // batch for this lane's B column

    // remote slot base for section 0 + deltas for other sections
    uint32_t radr0[8];
    uint32_t md0;
    {
        uint32_t slot0 = smem_u32 + 64 +
            (uint32_t)(ubb * HP_STRIDE + rank * 16 + (uu >> 1)) * 8 + (uu & 1) * 4;
#pragma unroll
        for (int c8 = 0; c8 < 8; c8++)
            asm("mapa.shared::cluster.u32 %0, %1, %2;"
                : "=r"(radr0[c8]) : "r"(slot0), "r"(c8));
        md0 = smem_u32 - slot0;          // remote mbar(sec) = radr + md0 + sec*8
    }

    float creg[2] = {0.f, 0.f};          // c-state for owned groups (j=0,1)
    int ph[8] = {0, 0, 0, 0, 0, 0, 0, 0};

    for (int s = 0; s < S_; s++) {
        const int p = s & 1;
        const int q = p ^ 1;

        if (tid == 0) {
#pragma unroll
            for (int g = 0; g < 4; g++)
                MBAR_EXPECT(smem_u32 + (g * 2 + q) * 8, 4096);
        }

        // prefetch P rows for both owned groups (overlaps waits/mma)
        float pv[2][4];
#pragma unroll
        for (int j = 0; j < 2; j++) {
            int g = 2 * j + half;
            int bb = g * 4 + ubb;
            int sk = sk_s[bb * S_ + s];
            int an = an_s[bb * S_ + s];
            const float* P = an ? g_P1 : g_P0;
            const float* Pb = P + (size_t)sk * G4 + 32 * rank + uu;
            pv[j][0] = __ldg(Pb);
            pv[j][1] = __ldg(Pb + H_);
            pv[j][2] = __ldg(Pb + 2 * H_);
            pv[j][3] = __ldg(Pb + 3 * H_);
        }

#pragma unroll
        for (int g = 0; g < 4; g++) {
            const int sec = g * 2 + p;
            if (s > 0) {
                mbar_wait_cluster(smem_u32 + sec * 8, ph[sec]);
                ph[sec] ^= 1;
            }

            // ---- HMMA gate matmul for group g ----
            const unsigned long long* hb = hp + sec * HP_GB + n4 * HP_STRIDE;
            float acc1[2][4], acc2[2][4];
#pragma unroll
            for (int a = 0; a < 2; a++)
#pragma unroll
                for (int e = 0; e < 4; e++) { acc1[a][e] = 0.f; acc2[a][e] = 0.f; }

#pragma unroll
            for (int t = 0; t < 16; t++) {
                int j0 = t * 8 + (l & 3);
                uint2 v0 = *(const uint2*)(hb + j0);
                uint2 v1 = *(const uint2*)(hb + j0 + 4);
                uint32_t b0 = (l < 16) ? v0.x : v0.y;
                uint32_t b1 = (l < 16) ? v1.x : v1.y;
                mma16816(acc1[t & 1], ah[t], b0, b1);
                mma16816(acc2[t & 1], al[t], b0, b1);
            }
            float gsum[4];
#pragma unroll
            for (int e = 0; e < 4; e++) {
                float comb = (acc1[0][e] + acc1[1][e]) + (acc2[0][e] + acc2[1][e]);
                gsum[e] = comb + __shfl_xor_sync(0xFFFFFFFFu, comb, 2);
            }
            if ((l & 3) < 2) {
                int n  = (l & 3) * 2;
                int r0 = 16 * w + (l >> 2);
                gp[r0 * 5 + n]           = gsum[0];
                gp[r0 * 5 + n + 1]       = gsum[1];
                gp[(r0 + 8) * 5 + n]     = gsum[2];
                gp[(r0 + 8) * 5 + n + 1] = gsum[3];
            }
            __syncthreads();

            // ---- update for group g (its owning 128-thread half) ----
            if ((g & 1) == half) {
                const int j = g >> 1;
                float v[4];
#pragma unroll
                for (int gg4 = 0; gg4 < 4; gg4++)
                    v[gg4] = gp[(gg4 * 32 + uu) * 5 + ubb] + pv[j][gg4];
                float ig = sig_a(v[0]), fg = sig_a(v[1]);
                float gg = tanh_a(v[2]), og = sig_a(v[3]);
                float c = fg * creg[j] + ig * gg;
                creg[j] = c;
                float h = og * tanh_a(c);
                int b = cid * 16 + g * 4 + ubb;
                out[(size_t)b * S_ * H_ + (size_t)s * H_ + 32 * rank + uu] = h;

                __nv_bfloat16 hh = __float2bfloat16(h);
                float lr = h - __bfloat162float(hh);
                __nv_bfloat16 hl = __float2bfloat16(lr);
                uint32_t myhi = __bfloat16_as_ushort(hh);
                uint32_t mylo = __bfloat16_as_ushort(hl);
                uint32_t obhi = __shfl_xor_sync(0xFFFFFFFFu, myhi, 1);
                uint32_t oblo = __shfl_xor_sync(0xFFFFFFFFu, mylo, 1);
                uint32_t payload = (uu & 1) ? ((mylo << 16) | oblo)
                                            : ((obhi << 16) | myhi);
                uint32_t secD = (uint32_t)(g * 2 + q) * (HP_GB * 8);
                uint32_t mbD  = md0 + (uint32_t)(g * 2 + q) * 8;
#pragma unroll
                for (int c8 = 0; c8 < 8; c8++)
                    st_async_u32(radr0[c8] + secD, payload, radr0[c8] + mbD);
            }
            __syncthreads();   // protect gp before next section's writes
        }
    }

    // drain: final sends target buffer 0 of each group
    mbar_wait_cluster(smem_u32 + 0 * 8, ph[0]);
    mbar_wait_cluster(smem_u32 + 2 * 8, ph[2]);
    mbar_wait_cluster(smem_u32 + 4 * 8, ph[4]);
    mbar_wait_cluster(smem_u32 + 6 * 8, ph[6]);
}

// ---------------------------------------------------------------------------
// prefix-softmax attention v2: parallel scan, 2 CTAs per batch
__global__ void __launch_bounds__(128)
attnscan_kernel() {
    int b = blockIdx.y;
    int half = blockIdx.x;
    int t = threadIdx.x;
    __shared__ float e_s[S_];
    __shared__ float dinv[S_];
    __shared__ float wsum[4];

    const float* ab = g_att + b * S_;
    float l[4];
    float run = 0.f;
#pragma unroll
    for (int i = 0; i < 4; i++) {
        float e = __expf(ab[t * 4 + i]);
        e_s[t * 4 + i] = e;
        run += e;
        l[i] = run;
    }
    int lane = t & 31, wi = t >> 5;
    float v = run;
#pragma unroll
    for (int off = 1; off < 32; off <<= 1) {
        float n = __shfl_up_sync(0xFFFFFFFFu, v, off);
        if (lane >= off) v += n;
    }
    if (lane == 31) wsum[wi] = v;
    __syncthreads();
    float woff = 0.f;
#pragma unroll
    for (int k = 0; k < 4; k++)
        if (k < wi) woff += wsum[k];
    float toff = woff + (v - run);
#pragma unroll
    for (int i = 0; i < 4; i++)
        dinv[t * 4 + i] = __fdividef(1.0f, toff + l[i]);
    __syncthreads();

    int d = half * 128 + t;
    const float* ob = g_out + (size_t)b * S_ * H_ + d;
    float acc = 0.f, cum = 0.f;
    for (int s = 0; s < S_; s++) {
        float o = __ldg(ob + (size_t)s * H_);
        acc = fmaf(e_s[s], o, acc);
        float ao = acc * dinv[s];
        size_t base = ((size_t)b * S_ + s) * IN_;
        __nv_bfloat16 ch = __float2bfloat16(cum);
        g_finH[base + d] = ch;
        g_finL[base + d] = __float2bfloat16(cum - __bfloat162float(ch));
        __nv_bfloat16 oh = __float2bfloat16(o);
        g_finH[base + H_ + d] = oh;
        g_finL[base + H_ + d] = __float2bfloat16(o - __bfloat162float(oh));
        cum += ao;
    }
}

// ---------------------------------------------------------------------------
// fc GEMM on HMMA (mma.sync bf16, hi/lo split, 3 terms)
#define FC_STAGE 65536
#define FC_SMEM (2 * FC_STAGE + 1024)

__global__ void __launch_bounds__(256, 1)
fcgemm_kernel(float* __restrict__ res) {
    extern __shared__ char dsm[];
    __shared__ float fcb_s[128];
    uint32_t sb = (s2u(dsm) + 1023u) & ~1023u;

    int tid = threadIdx.x;
    int wid = tid >> 5, lane = tid & 31;
    int ntile = blockIdx.x, mtile = blockIdx.y;
    size_t mBase = (size_t)mtile * 128;
    int nBase = ntile * 128;

    if (tid < 128) fcb_s[tid] = g_fcb[nBase + tid];

    const __nv_bfloat16* srcs[4] = {
        g_finH + mBase * IN_, g_finL + mBase * IN_,
        g_fwH + (size_t)nBase * IN_, g_fwL + (size_t)nBase * IN_ };

    auto stage = [&](int c) {
        uint32_t base = sb + (uint32_t)(c & 1) * FC_STAGE;
        int k0 = c * 64;
#pragma unroll
        for (int i = 0; i < 16; i++) {
            int idx = tid + 256 * i;
            int tile = idx >> 10;
            int w = idx & 1023;
            int rr = w >> 3, gg = w & 7;
            uint32_t dst = base + tile * 16384 + SWZ(w * 16);
            const __nv_bfloat16* src = srcs[tile] + (size_t)rr * IN_ + k0 + gg * 8;
            cpa16(dst, src);
        }
        CPA_COMMIT();
    };

    const int mrow0 = (wid & 1) * 64;
    const int ncol0 = (wid >> 1) * 32;

    float acc[4][4][4];
#pragma unroll
    for (int mi = 0; mi < 4; mi++)
#pragma unroll
        for (int nj = 0; nj < 4; nj++)
#pragma unroll
            for (int q = 0; q < 4; q++) acc[mi][nj][q] = 0.f;

    stage(0);
    stage(1);

    for (int c = 0; c < 8; c++) {
        if (c < 7) cpa_wait<1>(); else cpa_wait<0>();
        __syncthreads();
        uint32_t base = sb + (uint32_t)(c & 1) * FC_STAGE;

#pragma unroll
        for (int ks = 0; ks < 4; ks++) {
            int kw = ks * 16 + ((lane >> 4) << 3);
            uint32_t a_h[4][4], a_l[4][4];
#pragma unroll
            for (int mi = 0; mi < 4; mi++) {
                int row = mrow0 + mi * 16 + (lane & 15);
                uint32_t off = SWZ((uint32_t)(row * 128 + kw * 2));
                ldsm4(a_h[mi], base + off);
                ldsm4(a_l[mi], base + 16384 + off);
            }
            uint32_t b_h[2][4], b_l[2][4];
#pragma unroll
            for (int bj = 0; bj < 2; bj++) {
                int nrow = ncol0 + bj * 16 + (lane & 15);
                uint32_t off = SWZ((uint32_t)(nrow * 128 + kw * 2));
                ldsm4(b_h[bj], base + 32768 + off);
                ldsm4(b_l[bj], base + 49152 + off);
            }
#pragma unroll
            for (int mi = 0; mi < 4; mi++)
#pragma unroll
                for (int nj = 0; nj < 4; nj++) {
                    int bj = nj >> 1, sel = nj & 1;
                    mma16816(acc[mi][nj], a_h[mi], b_h[bj][sel], b_h[bj][sel + 2]);
                    mma16816(acc[mi][nj], a_l[mi], b_h[bj][sel], b_h[bj][sel + 2]);
                    mma16816(acc[mi][nj], a_h[mi], b_l[bj][sel], b_l[bj][sel + 2]);
                }
        }
        __syncthreads();
        if (c + 2 < 8) stage(c + 2);
    }

#pragma unroll
    for (int mi = 0; mi < 4; mi++) {
        int r0 = (int)mBase + mrow0 + mi * 16 + (lane >> 2);
#pragma unroll
        for (int nj = 0; nj < 4; nj++) {
            int lc = ncol0 + nj * 8 + (lane & 3) * 2;
            int col = nBase + lc;
            if (col < NC) {
                float b0 = fcb_s[lc], b1 = fcb_s[lc + 1];
                float2 v0 = make_float2(sig_a(acc[mi][nj][0] + b0),
                                        sig_a(acc[mi][nj][1] + b1));
                float2 v1 = make_float2(sig_a(acc[mi][nj][2] + b0),
                                        sig_a(acc[mi][nj][3] + b1));
                *reinterpret_cast<float2*>(res + (size_t)r0 * NC + col) = v0;
                *reinterpret_cast<float2*>(res + (size_t)(r0 + 8) * NC + col) = v1;
            }
        }
    }
}

// ---------------------------------------------------------------------------
extern "C" void kernel_launch(void* const* d_in, const int* in_sizes, int n_in,
                              void* d_out, int out_size) {
    const int*   skill      = (const int*)  d_in[0];
    const int*   answer     = (const int*)  d_in[1];
    const float* skill_emb  = (const float*)d_in[2];
    const float* answer_emb = (const float*)d_in[3];
    const float* Wih        = (const float*)d_in[4];
    const float* Whh        = (const float*)d_in[5];
    const float* bih        = (const float*)d_in[6];
    const float* bhh        = (const float*)d_in[7];
    const float* mlp_W      = (const float*)d_in[8];
    const float* mlp_b      = (const float*)d_in[9];
    const float* sim_W      = (const float*)d_in[10];
    const float* fc_W       = (const float*)d_in[11];
    const float* fc_b       = (const float*)d_in[12];

    float* res = (float*)d_out;
    float* sa  = (float*)d_out + RES_ELEMS;

    float* P1_p;  cudaGetSymbolAddress((void**)&P1_p,  g_P1);
    float* P0_p;  cudaGetSymbolAddress((void**)&P0_p,  g_P0);
    float* qb_p;  cudaGetSymbolAddress((void**)&qb_p,  g_qb);
    float* out_p; cudaGetSymbolAddress((void**)&out_p, g_out);
    float* att_p; cudaGetSymbolAddress((void**)&att_p, g_att);

    cudaFuncSetAttribute(lstm_kernel,
                         cudaFuncAttributeMaxDynamicSharedMemorySize, LSTM_SMEM);
    cudaFuncSetAttribute(fcgemm_kernel,
                         cudaFuncAttributeMaxDynamicSharedMemorySize, FC_SMEM);

    qbias_kernel<<<8, 256>>>(Wih, answer_emb, bih, bhh);
    embed_kernel<<<MTOT, 256>>>(skill, answer, skill_emb, answer_emb, sa);
    convw_kernel<<<(1024 * IN_ + 255) / 256, 256>>>(fc_W, fc_b);

    {
        dim3 grid(G4 / 64, (1000 + 63) / 64);
        gemm_kernel<<<grid, 256>>>(skill_emb, H_, Wih,      IN_, qb_p + G4, P1_p,
                                   1000, G4, H_, 0, nullptr, nullptr);
        gemm_kernel<<<grid, 256>>>(skill_emb, H_, Wih + H_, IN_, qb_p,      P0_p,
                                   1000, G4, H_, 0, nullptr, nullptr);
    }

    lstm_kernel<<<32, 256, LSTM_SMEM>>>(skill, answer, Whh, out_p);

    // mlp + attdot fused
    {
        dim3 grid((AD + 63) / 64, MTOT / 64);
        gemm_kernel<<<grid, 256>>>(out_p, H_, mlp_W, H_, mlp_b, nullptr,
                                   MTOT, AD, H_, 3, sim_W, att_p);
    }

    {
        dim3 grid(2, B_);
        attnscan_kernel<<<grid, 128>>>();
    }

    {
        dim3 grid(8, 256);   // ntile, mtile
        fcgemm_kernel<<<grid, 256, FC_SMEM>>>(res);
    }
}

// round 16
// speedup vs baseline: 1.5970x; 1.5970x over previous
#include <cuda_runtime.h>
#include <cuda_bf16.h>
#include <math.h>
#include <stdint.h>

#define B_    64
#define S_    512
#define H_    256
#define IN_   512
#define G4    1024      // 4*H
#define NC    1000
#define AD    80
#define MTOT  (B_*S_)   // 32768
#define RES_ELEMS (MTOT*NC)

// ---------------- scratch (device globals) ---------------------------------
__device__ float g_P1[1000 * G4];
__device__ float g_P0[1000 * G4];
__device__ float g_qb[2 * G4];
__device__ float g_out  [MTOT * H_];
__device__ float g_att  [MTOT];
__device__ __nv_bfloat16 g_finH[MTOT * IN_];
__device__ __nv_bfloat16 g_finL[MTOT * IN_];
__device__ __nv_bfloat16 g_fwH[1024 * IN_];
__device__ __nv_bfloat16 g_fwL[1024 * IN_];
__device__ float g_fcb[1024];

// ---------------- helpers ---------------------------------------------------
__device__ __forceinline__ unsigned long long fma2(unsigned long long a,
                                                   unsigned long long b,
                                                   unsigned long long c) {
    unsigned long long d;
    asm("fma.rn.f32x2 %0, %1, %2, %3;" : "=l"(d) : "l"(a), "l"(b), "l"(c));
    return d;
}
__device__ __forceinline__ float f2sum(unsigned long long v) {
    float lo, hi;
    asm("mov.b64 {%0, %1}, %2;" : "=f"(lo), "=f"(hi) : "l"(v));
    return lo + hi;
}
__device__ __forceinline__ uint32_t s2u(const void* p) {
    uint32_t a;
    asm("{ .reg .u64 t; cvta.to.shared.u64 t, %1; cvt.u32.u64 %0, t; }"
        : "=r"(a) : "l"(p));
    return a;
}
__device__ __forceinline__ float tanh_a(float x) {
    float y;
    asm("tanh.approx.f32 %0, %1;" : "=f"(y) : "f"(x));
    return y;
}
__device__ __forceinline__ float sig_a(float x) {
    return fmaf(tanh_a(0.5f * x), 0.5f, 0.5f);
}

#define SWZ(o) ((o) ^ (((o) >> 3) & 0x70))

__device__ __forceinline__ void cpa16(uint32_t dst, const void* src) {
    asm volatile("cp.async.cg.shared.global [%0], [%1], 16;" :: "r"(dst), "l"(src) : "memory");
}
#define CPA_COMMIT() asm volatile("cp.async.commit_group;" ::: "memory")
template<int N> __device__ __forceinline__ void cpa_wait() {
    asm volatile("cp.async.wait_group %0;" :: "n"(N) : "memory");
}

__device__ __forceinline__ void ldsm4(uint32_t (&r)[4], uint32_t addr) {
    asm volatile("ldmatrix.sync.aligned.m8n8.x4.shared.b16 {%0,%1,%2,%3}, [%4];"
        : "=r"(r[0]), "=r"(r[1]), "=r"(r[2]), "=r"(r[3]) : "r"(addr));
}
__device__ __forceinline__ void mma16816(float (&d)[4], const uint32_t (&a)[4],
                                         uint32_t b0, uint32_t b1) {
    asm volatile("mma.sync.aligned.m16n8k16.row.col.f32.bf16.bf16.f32 "
        "{%0,%1,%2,%3}, {%4,%5,%6,%7}, {%8,%9}, {%0,%1,%2,%3};"
        : "+f"(d[0]), "+f"(d[1]), "+f"(d[2]), "+f"(d[3])
        : "r"(a[0]), "r"(a[1]), "r"(a[2]), "r"(a[3]), "r"(b0), "r"(b1));
}

#define MBAR_INIT(a, cnt) asm volatile("mbarrier.init.shared.b64 [%0], %1;" :: "r"(a), "r"(cnt) : "memory")
#define MBAR_EXPECT(a, bytes) asm volatile("mbarrier.arrive.expect_tx.shared.b64 _, [%0], %1;" :: "r"(a), "r"(bytes) : "memory")
__device__ __forceinline__ void mbar_wait_cluster(uint32_t mbar, uint32_t parity) {
    uint32_t done;
    asm volatile(
        "{\n\t.reg .pred p;\n\t"
        "mbarrier.try_wait.parity.acquire.cluster.shared::cta.b64 p, [%1], %2;\n\t"
        "selp.b32 %0, 1, 0, p;\n\t}"
        : "=r"(done) : "r"(mbar), "r"(parity) : "memory");
    if (!done) {
        asm volatile(
            "{\n\t.reg .pred P1;\n\t"
            "WL_%=:\n\t"
            "mbarrier.try_wait.parity.acquire.cluster.shared::cta.b64 P1, [%0], %1, 0x989680;\n\t"
            "@P1 bra.uni WD_%=;\n\t"
            "bra.uni WL_%=;\n\t"
            "WD_%=:\n\t}"
            :: "r"(mbar), "r"(parity) : "memory");
    }
}
__device__ __forceinline__ void st_async_u32(uint32_t addr, uint32_t val, uint32_t mbar) {
    asm volatile("st.async.shared::cluster.mbarrier::complete_tx::bytes.b32 [%0], %1, [%2];"
                 :: "r"(addr), "r"(val), "r"(mbar) : "memory");
}

__device__ __forceinline__ void packhl(float2 v, uint32_t& hi, uint32_t& lo) {
    __nv_bfloat16 h0 = __float2bfloat16(v.x), h1 = __float2bfloat16(v.y);
    hi = ((uint32_t)__bfloat16_as_ushort(h1) << 16) | __bfloat16_as_ushort(h0);
    __nv_bfloat16 l0 = __float2bfloat16(v.x - __bfloat162float(h0));
    __nv_bfloat16 l1 = __float2bfloat16(v.y - __bfloat162float(h1));
    lo = ((uint32_t)__bfloat16_as_ushort(l1) << 16) | __bfloat16_as_ushort(l0);
}

// ---------------------------------------------------------------------------
__global__ void qbias_kernel(const float* __restrict__ Wih,
                             const float* __restrict__ answer_emb,
                             const float* __restrict__ bih,
                             const float* __restrict__ bhh) {
    int idx = blockIdx.x * blockDim.x + threadIdx.x;
    if (idx >= 2 * G4) return;
    int a = idx >> 10;
    int row = idx & (G4 - 1);
    int off = (a == 1) ? H_ : 0;
    float s = bih[row] + bhh[row];
    const float* wr = Wih + (size_t)row * IN_ + off;
    const float* ar = answer_emb + a * H_;
#pragma unroll 4
    for (int k = 0; k < H_; k++) s += wr[k] * ar[k];
    g_qb[idx] = s;
}

// ---------------------------------------------------------------------------
__global__ void embed_kernel(const int* __restrict__ skill,
                             const int* __restrict__ answer,
                             const float* __restrict__ skill_emb,
                             const float* __restrict__ answer_emb,
                             float* __restrict__ sa) {
    int r = blockIdx.x;
    int t = threadIdx.x;
    int sk = skill[r];
    int an = answer[r];
    float se = skill_emb[sk * H_ + t];
    float ae = answer_emb[an * H_ + t];
    float* o = sa + (size_t)r * IN_;
    if (an == 1) { o[t] = se; o[H_ + t] = ae; }
    else         { o[t] = ae; o[H_ + t] = se; }
    if (t == 0) g_att[r] = 0.f;
}

// ---------------------------------------------------------------------------
__global__ void convw_kernel(const float* __restrict__ fc_W,
                             const float* __restrict__ fc_b) {
    int idx = blockIdx.x * blockDim.x + threadIdx.x;
    if (idx >= 1024 * IN_) return;
    int row = idx >> 9;
    float x = (row < NC) ? fc_W[(size_t)row * IN_ + (idx & 511)] : 0.f;
    __nv_bfloat16 h = __float2bfloat16(x);
    g_fwH[idx] = h;
    g_fwL[idx] = __float2bfloat16(x - __bfloat162float(h));
    if (idx < 1024) g_fcb[idx] = (idx < NC) ? fc_b[idx] : 0.f;
}

// ---------------------------------------------------------------------------
// fp32 GEMM (f32x2) — P tables (act 0) and mlp+attdot fusion (act 3).
__global__ void gemm_kernel(const float* __restrict__ A, int lda,
                            const float* __restrict__ Bm, int ldb,
                            const float* __restrict__ bias,
                            float* __restrict__ C,
                            int M, int N, int K, int act,
                            const float* __restrict__ simW,
                            float* __restrict__ attO) {
    __shared__ float2 As2[8][64];
    __shared__ float2 Bs2[8][64];
    __shared__ float simW_s[128];

    int tid = threadIdx.x;
    int tx = tid & 15;
    int ty = tid >> 4;
    int rowBase = blockIdx.y * 64;
    int colBase = blockIdx.x * 64;
    int ldRow = tid >> 2;
    int ldCol = (tid & 3) * 4;

    if (act == 3 && tid < 128) {
        int c = colBase + tid;
        simW_s[tid] = (tid < 64 && c < N) ? simW[c] : 0.f;
    }

    unsigned long long acc[4][4];
#pragma unroll
    for (int i = 0; i < 4; i++)
#pragma unroll
        for (int j = 0; j < 4; j++) acc[i][j] = 0ULL;

    for (int k0 = 0; k0 < K; k0 += 16) {
        int arow = rowBase + ldRow; if (arow > M - 1) arow = M - 1;
        float4 av = *reinterpret_cast<const float4*>(A + (size_t)arow * lda + k0 + ldCol);
        As2[ldCol / 2][ldRow]     = make_float2(av.x, av.y);
        As2[ldCol / 2 + 1][ldRow] = make_float2(av.z, av.w);
        int n = colBase + ldRow;
        float4 bv = make_float4(0.f, 0.f, 0.f, 0.f);
        if (n < N)
            bv = *reinterpret_cast<const float4*>(Bm + (size_t)n * ldb + k0 + ldCol);
        Bs2[ldCol / 2][ldRow]     = make_float2(bv.x, bv.y);
        Bs2[ldCol / 2 + 1][ldRow] = make_float2(bv.z, bv.w);
        __syncthreads();

#pragma unroll
        for (int kk2 = 0; kk2 < 8; kk2++) {
            ulonglong2 aA = *reinterpret_cast<const ulonglong2*>(&As2[kk2][ty * 4]);
            ulonglong2 aB = *reinterpret_cast<const ulonglong2*>(&As2[kk2][ty * 4 + 2]);
            unsigned long long a2[4] = {aA.x, aA.y, aB.x, aB.y};
            unsigned long long b2[4];
#pragma unroll
            for (int j = 0; j < 4; j++)
                b2[j] = *reinterpret_cast<const unsigned long long*>(&Bs2[kk2][tx + 16 * j]);
#pragma unroll
            for (int i = 0; i < 4; i++)
#pragma unroll
                for (int j = 0; j < 4; j++)
                    acc[i][j] = fma2(a2[i], b2[j], acc[i][j]);
        }
        __syncthreads();
    }

    if (act == 3) {
#pragma unroll
        for (int i = 0; i < 4; i++) {
            int row = rowBase + ty * 4 + i;
            float part = 0.f;
#pragma unroll
            for (int j = 0; j < 4; j++) {
                int lc = tx + 16 * j;
                int col = colBase + lc;
                if (col < N) {
                    float v = f2sum(acc[i][j]) + bias[col];
                    part = fmaf(tanh_a(v), simW_s[lc], part);
                }
            }
            atomicAdd(attO + row, part);
        }
        return;
    }

#pragma unroll
    for (int i = 0; i < 4; i++) {
        int row = rowBase + ty * 4 + i;
        if (row >= M) continue;
#pragma unroll
        for (int j = 0; j < 4; j++) {
            int col = colBase + tx + 16 * j;
            if (col < N) {
                float v = f2sum(acc[i][j]);
                if (bias) v += bias[col];
                C[(size_t)row * N + col] = v;
            }
        }
    }
}

// ---------------------------------------------------------------------------
// LSTM v12 = r14 two-group pipeline + per-group double-buffered gp (one
// __syncthreads per section instead of two). 8 clusters x 8 CTAs x 8 batches.
#define HP_STRIDE 132                 // u64 per batch
#define HP_GB     (4 * HP_STRIDE)     // 528 u64 per (group,buffer) section
// floats: mbar 8 | hp 4*528 u64 = 4224 | gp 2*640 | c 256 | sk 4096 | an 4096
#define LSTM_SMEM ((8 + 4224 + 1280 + 256 + 4096 + 4096) * 4)

__global__ void __cluster_dims__(8, 1, 1) __launch_bounds__(256, 1)
lstm_kernel(const int* __restrict__ skill, const int* __restrict__ answer,
            const float* __restrict__ Whh, float* __restrict__ out) {
    extern __shared__ float smem[];
    uint32_t smem_u32 = s2u(smem);
    unsigned long long* hp = (unsigned long long*)(smem + 8);   // [4 sec][528]
    float* gp  = smem + 8 + 4224;        // [2 grp][128 rows][5]
    float* c_s = gp + 1280;              // [2][128]
    int* sk_s  = (int*)(c_s + 256);      // [8][512]
    int* an_s  = sk_s + 8 * S_;          // [8][512]

    int tid  = threadIdx.x;
    int w    = tid >> 5;
    int l    = tid & 31;
    int rank = blockIdx.x & 7;
    int cid  = blockIdx.x >> 3;

    // ---- one-time: Whh -> bf16 hi/lo A-fragments in registers ----
    uint32_t ah[16][4], al[16][4];
    {
        int rl0 = 16 * w + (l >> 2);
        int rl1 = rl0 + 8;
        size_t rowA = (size_t)((rl0 >> 5) * H_ + rank * 32 + (rl0 & 31)) * H_;
        size_t rowB = (size_t)((rl1 >> 5) * H_ + rank * 32 + (rl1 & 31)) * H_;
#pragma unroll
        for (int t = 0; t < 16; t++) {
            int k = t * 16 + (l & 3) * 2;
            packhl(*(const float2*)(Whh + rowA + k),     ah[t][0], al[t][0]);
            packhl(*(const float2*)(Whh + rowB + k),     ah[t][1], al[t][1]);
            packhl(*(const float2*)(Whh + rowA + k + 8), ah[t][2], al[t][2]);
            packhl(*(const float2*)(Whh + rowB + k + 8), ah[t][3], al[t][3]);
        }
    }

    // init smem
    for (int i = tid; i < 4 * HP_GB; i += 256) hp[i] = 0ULL;
    c_s[tid] = 0.f;
    for (int i = tid; i < 8 * S_; i += 256) {
        int bb = i >> 9, ss = i & (S_ - 1);
        int ridx = (cid * 8 + bb) * S_ + ss;
        sk_s[i] = skill[ridx];
        an_s[i] = answer[ridx];
    }
    if (tid == 0) {
#pragma unroll
        for (int m = 0; m < 4; m++) MBAR_INIT(smem_u32 + m * 8, 1);
    }
    __syncthreads();
    asm volatile("barrier.cluster.arrive.aligned;" ::: "memory");
    asm volatile("barrier.cluster.wait.aligned;" ::: "memory");

    const int myg  = tid >> 7;           // update group of this thread
    const int utid = tid & 127;
    const int uu   = utid & 31;
    const int ubb  = utid >> 5;          // batch within group
    const int n4   = (l >> 2) & 3;       // batch for this lane's B column

    uint32_t radr0[8];
    uint32_t md0;
    {
        uint32_t slot0 = smem_u32 + 32 +
            (uint32_t)(ubb * HP_STRIDE + rank * 16 + (uu >> 1)) * 8 + (uu & 1) * 4;
#pragma unroll
        for (int c8 = 0; c8 < 8; c8++)
            asm("mapa.shared::cluster.u32 %0, %1, %2;"
                : "=r"(radr0[c8]) : "r"(slot0), "r"(c8));
        md0 = smem_u32 - slot0;
    }

    int ph[4] = {0, 0, 0, 0};

    for (int s = 0; s < S_; s++) {
        const int p = s & 1;
        const int q = p ^ 1;

        if (tid == 0) {
            MBAR_EXPECT(smem_u32 + (0 * 2 + q) * 8, 4096);
            MBAR_EXPECT(smem_u32 + (1 * 2 + q) * 8, 4096);
        }

        float pv[4];
        {
            int sk = sk_s[(myg * 4 + ubb) * S_ + s];
            int an = an_s[(myg * 4 + ubb) * S_ + s];
            const float* P = an ? g_P1 : g_P0;
            const float* Pb = P + (size_t)sk * G4 + 32 * rank + uu;
            pv[0] = __ldg(Pb);
            pv[1] = __ldg(Pb + H_);
            pv[2] = __ldg(Pb + 2 * H_);
            pv[3] = __ldg(Pb + 3 * H_);
        }

#pragma unroll
        for (int g = 0; g < 2; g++) {
            const int sec = g * 2 + p;
            if (s > 0) {
                mbar_wait_cluster(smem_u32 + sec * 8, ph[sec]);
                ph[sec] ^= 1;
            }

            // ---- HMMA gate matmul for group g ----
            const unsigned long long* hb = hp + sec * HP_GB + n4 * HP_STRIDE;
            float acc1[2][4], acc2[2][4];
#pragma unroll
            for (int a = 0; a < 2; a++)
#pragma unroll
                for (int e = 0; e < 4; e++) { acc1[a][e] = 0.f; acc2[a][e] = 0.f; }

#pragma unroll
            for (int t = 0; t < 16; t++) {
                int j0 = t * 8 + (l & 3);
                uint2 v0 = *(const uint2*)(hb + j0);
                uint2 v1 = *(const uint2*)(hb + j0 + 4);
                uint32_t b0 = (l < 16) ? v0.x : v0.y;
                uint32_t b1 = (l < 16) ? v1.x : v1.y;
                mma16816(acc1[t & 1], ah[t], b0, b1);
                mma16816(acc2[t & 1], al[t], b0, b1);
            }
            float gsum[4];
#pragma unroll
            for (int e = 0; e < 4; e++) {
                float comb = (acc1[0][e] + acc1[1][e]) + (acc2[0][e] + acc2[1][e]);
                gsum[e] = comb + __shfl_xor_sync(0xFFFFFFFFu, comb, 2);
            }
            float* gpg = gp + g * 640;
            if ((l & 3) < 2) {
                int n  = (l & 3) * 2;
                int r0 = 16 * w + (l >> 2);
                gpg[r0 * 5 + n]           = gsum[0];
                gpg[r0 * 5 + n + 1]       = gsum[1];
                gpg[(r0 + 8) * 5 + n]     = gsum[2];
                gpg[(r0 + 8) * 5 + n + 1] = gsum[3];
            }
            __syncthreads();   // single sync: gp[g] now complete

            // ---- update for group g (only its 128 threads) ----
            if (myg == g) {
                float v[4];
#pragma unroll
                for (int gg4 = 0; gg4 < 4; gg4++)
                    v[gg4] = gpg[(gg4 * 32 + uu) * 5 + ubb] + pv[gg4];
                float ig = sig_a(v[0]), fg = sig_a(v[1]);
                float gg = tanh_a(v[2]), og = sig_a(v[3]);
                float c = fg * c_s[tid] + ig * gg;
                c_s[tid] = c;
                float h = og * tanh_a(c);
                int b = cid * 8 + g * 4 + ubb;
                out[(size_t)b * S_ * H_ + (size_t)s * H_ + 32 * rank + uu] = h;

                __nv_bfloat16 hh = __float2bfloat16(h);
                float lr = h - __bfloat162float(hh);
                __nv_bfloat16 hl = __float2bfloat16(lr);
                uint32_t myhi = __bfloat16_as_ushort(hh);
                uint32_t mylo = __bfloat16_as_ushort(hl);
                uint32_t obhi = __shfl_xor_sync(0xFFFFFFFFu, myhi, 1);
                uint32_t oblo = __shfl_xor_sync(0xFFFFFFFFu, mylo, 1);
                uint32_t payload = (uu & 1) ? ((mylo << 16) | oblo)
                                            : ((obhi << 16) | myhi);
                uint32_t secD = (uint32_t)(g * 2 + q) * (HP_GB * 8);
                uint32_t mbD  = md0 + (uint32_t)(g * 2 + q) * 8;
#pragma unroll
                for (int c8 = 0; c8 < 8; c8++)
                    st_async_u32(radr0[c8] + secD, payload, radr0[c8] + mbD);
            }
        }
    }

    mbar_wait_cluster(smem_u32 + 0 * 8, ph[0]);
    mbar_wait_cluster(smem_u32 + 2 * 8, ph[2]);
}

// ---------------------------------------------------------------------------
// prefix-softmax attention v2: parallel scan, 2 CTAs per batch
__global__ void __launch_bounds__(128)
attnscan_kernel() {
    int b = blockIdx.y;
    int half = blockIdx.x;
    int t = threadIdx.x;
    __shared__ float e_s[S_];
    __shared__ float dinv[S_];
    __shared__ float wsum[4];

    const float* ab = g_att + b * S_;
    float l[4];
    float run = 0.f;
#pragma unroll
    for (int i = 0; i < 4; i++) {
        float e = __expf(ab[t * 4 + i]);
        e_s[t * 4 + i] = e;
        run += e;
        l[i] = run;
    }
    int lane = t & 31, wi = t >> 5;
    float v = run;
#pragma unroll
    for (int off = 1; off < 32; off <<= 1) {
        float n = __shfl_up_sync(0xFFFFFFFFu, v, off);
        if (lane >= off) v += n;
    }
    if (lane == 31) wsum[wi] = v;
    __syncthreads();
    float woff = 0.f;
#pragma unroll
    for (int k = 0; k < 4; k++)
        if (k < wi) woff += wsum[k];
    float toff = woff + (v - run);
#pragma unroll
    for (int i = 0; i < 4; i++)
        dinv[t * 4 + i] = __fdividef(1.0f, toff + l[i]);
    __syncthreads();

    int d = half * 128 + t;
    const float* ob = g_out + (size_t)b * S_ * H_ + d;
    float acc = 0.f, cum = 0.f;
    for (int s = 0; s < S_; s++) {
        float o = __ldg(ob + (size_t)s * H_);
        acc = fmaf(e_s[s], o, acc);
        float ao = acc * dinv[s];
        size_t base = ((size_t)b * S_ + s) * IN_;
        __nv_bfloat16 ch = __float2bfloat16(cum);
        g_finH[base + d] = ch;
        g_finL[base + d] = __float2bfloat16(cum - __bfloat162float(ch));
        __nv_bfloat16 oh = __float2bfloat16(o);
        g_finH[base + H_ + d] = oh;
        g_finL[base + H_ + d] = __float2bfloat16(o - __bfloat162float(oh));
        cum += ao;
    }
}

// ---------------------------------------------------------------------------
// fc GEMM on HMMA (mma.sync bf16, hi/lo split, 3 terms), 3-stage pipeline
#define FC_STAGE 65536
#define FC_SMEM (3 * FC_STAGE + 1024)

__global__ void __launch_bounds__(256, 1)
fcgemm_kernel(float* __restrict__ res) {
    extern __shared__ char dsm[];
    __shared__ float fcb_s[128];
    uint32_t sb = (s2u(dsm) + 1023u) & ~1023u;

    int tid = threadIdx.x;
    int wid = tid >> 5, lane = tid & 31;
    int ntile = blockIdx.x, mtile = blockIdx.y;
    size_t mBase = (size_t)mtile * 128;
    int nBase = ntile * 128;

    if (tid < 128) fcb_s[tid] = g_fcb[nBase + tid];

    const __nv_bfloat16* srcs[4] = {
        g_finH + mBase * IN_, g_finL + mBase * IN_,
        g_fwH + (size_t)nBase * IN_, g_fwL + (size_t)nBase * IN_ };

    auto stage = [&](int c) {
        uint32_t base = sb + (uint32_t)(c % 3) * FC_STAGE;
        int k0 = c * 64;
#pragma unroll
        for (int i = 0; i < 16; i++) {
            int idx = tid + 256 * i;
            int tile = idx >> 10;
            int w = idx & 1023;
            int rr = w >> 3, gg = w & 7;
            uint32_t dst = base + tile * 16384 + SWZ(w * 16);
            const __nv_bfloat16* src = srcs[tile] + (size_t)rr * IN_ + k0 + gg * 8;
            cpa16(dst, src);
        }
        CPA_COMMIT();
    };

    const int mrow0 = (wid & 1) * 64;
    const int ncol0 = (wid >> 1) * 32;

    float acc[4][4][4];
#pragma unroll
    for (int mi = 0; mi < 4; mi++)
#pragma unroll
        for (int nj = 0; nj < 4; nj++)
#pragma unroll
            for (int q = 0; q < 4; q++) acc[mi][nj][q] = 0.f;

    stage(0);
    stage(1);
    stage(2);

    for (int c = 0; c < 8; c++) {
        if (c < 6) cpa_wait<2>(); else if (c < 7) cpa_wait<1>(); else cpa_wait<0>();
        __syncthreads();
        uint32_t base = sb + (uint32_t)(c % 3) * FC_STAGE;

#pragma unroll
        for (int ks = 0; ks < 4; ks++) {
            int kw = ks * 16 + ((lane >> 4) << 3);
            uint32_t a_h[4][4], a_l[4][4];
#pragma unroll
            for (int mi = 0; mi < 4; mi++) {
                int row = mrow0 + mi * 16 + (lane & 15);
                uint32_t off = SWZ((uint32_t)(row * 128 + kw * 2));
                ldsm4(a_h[mi], base + off);
                ldsm4(a_l[mi], base + 16384 + off);
            }
            uint32_t b_h[2][4], b_l[2][4];
#pragma unroll
            for (int bj = 0; bj < 2; bj++) {
                int nrow = ncol0 + bj * 16 + (lane & 15);
                uint32_t off = SWZ((uint32_t)(nrow * 128 + kw * 2));
                ldsm4(b_h[bj], base + 32768 + off);
                ldsm4(b_l[bj], base + 49152 + off);
            }
#pragma unroll
            for (int mi = 0; mi < 4; mi++)
#pragma unroll
                for (int nj = 0; nj < 4; nj++) {
                    int bj = nj >> 1, sel = nj & 1;
                    mma16816(acc[mi][nj], a_h[mi], b_h[bj][sel], b_h[bj][sel + 2]);
                    mma16816(acc[mi][nj], a_l[mi], b_h[bj][sel], b_h[bj][sel + 2]);
                    mma16816(acc[mi][nj], a_h[mi], b_l[bj][sel], b_l[bj][sel + 2]);
                }
        }
        __syncthreads();
        if (c + 3 < 8) stage(c + 3);
    }

#pragma unroll
    for (int mi = 0; mi < 4; mi++) {
        int r0 = (int)mBase + mrow0 + mi * 16 + (lane >> 2);
#pragma unroll
        for (int nj = 0; nj < 4; nj++) {
            int lc = ncol0 + nj * 8 + (lane & 3) * 2;
            int col = nBase + lc;
            if (col < NC) {
                float b0 = fcb_s[lc], b1 = fcb_s[lc + 1];
                float2 v0 = make_float2(sig_a(acc[mi][nj][0] + b0),
                                        sig_a(acc[mi][nj][1] + b1));
                float2 v1 = make_float2(sig_a(acc[mi][nj][2] + b0),
                                        sig_a(acc[mi][nj][3] + b1));
                *reinterpret_cast<float2*>(res + (size_t)r0 * NC + col) = v0;
                *reinterpret_cast<float2*>(res + (size_t)(r0 + 8) * NC + col) = v1;
            }
        }
    }
}

// ---------------------------------------------------------------------------
extern "C" void kernel_launch(void* const* d_in, const int* in_sizes, int n_in,
                              void* d_out, int out_size) {
    const int*   skill      = (const int*)  d_in[0];
    const int*   answer     = (const int*)  d_in[1];
    const float* skill_emb  = (const float*)d_in[2];
    const float* answer_emb = (const float*)d_in[3];
    const float* Wih        = (const float*)d_in[4];
    const float* Whh        = (const float*)d_in[5];
    const float* bih        = (const float*)d_in[6];
    const float* bhh        = (const float*)d_in[7];
    const float* mlp_W      = (const float*)d_in[8];
    const float* mlp_b      = (const float*)d_in[9];
    const float* sim_W      = (const float*)d_in[10];
    const float* fc_W       = (const float*)d_in[11];
    const float* fc_b       = (const float*)d_in[12];

    float* res = (float*)d_out;
    float* sa  = (float*)d_out + RES_ELEMS;

    float* P1_p;  cudaGetSymbolAddress((void**)&P1_p,  g_P1);
    float* P0_p;  cudaGetSymbolAddress((void**)&P0_p,  g_P0);
    float* qb_p;  cudaGetSymbolAddress((void**)&qb_p,  g_qb);
    float* out_p; cudaGetSymbolAddress((void**)&out_p, g_out);
    float* att_p; cudaGetSymbolAddress((void**)&att_p, g_att);

    cudaFuncSetAttribute(lstm_kernel,
                         cudaFuncAttributeMaxDynamicSharedMemorySize, LSTM_SMEM);
    cudaFuncSetAttribute(fcgemm_kernel,
                         cudaFuncAttributeMaxDynamicSharedMemorySize, FC_SMEM);

    qbias_kernel<<<8, 256>>>(Wih, answer_emb, bih, bhh);
    embed_kernel<<<MTOT, 256>>>(skill, answer, skill_emb, answer_emb, sa);
    convw_kernel<<<(1024 * IN_ + 255) / 256, 256>>>(fc_W, fc_b);

    {
        dim3 grid(G4 / 64, (1000 + 63) / 64);
        gemm_kernel<<<grid, 256>>>(skill_emb, H_, Wih,      IN_, qb_p + G4, P1_p,
                                   1000, G4, H_, 0, nullptr, nullptr);
        gemm_kernel<<<grid, 256>>>(skill_emb, H_, Wih + H_, IN_, qb_p,      P0_p,
                                   1000, G4, H_, 0, nullptr, nullptr);
    }

    lstm_kernel<<<64, 256, LSTM_SMEM>>>(skill, answer, Whh, out_p);

    // mlp + attdot fused
    {
        dim3 grid((AD + 63) / 64, MTOT / 64);
        gemm_kernel<<<grid, 256>>>(out_p, H_, mlp_W, H_, mlp_b, nullptr,
                                   MTOT, AD, H_, 3, sim_W, att_p);
    }

    {
        dim3 grid(2, B_);
        attnscan_kernel<<<grid, 128>>>();
    }

    {
        dim3 grid(8, 256);   // ntile, mtile
        fcgemm_kernel<<<grid, 256, FC_SMEM>>>(res);
    }
}